// round 9
// baseline (speedup 1.0000x reference)
#include <cuda_runtime.h>
#include <stdint.h>

// ---------------------------------------------------------------------------
// TwoWL: 2-layer 2-WL coloring, N=256, M=65536. Output: 3 float32 histograms.
// Single persistent kernel; phases separated by software grid barriers.
// ---------------------------------------------------------------------------

#define NN 256
#define MM 65536
#define TAB 131072
#define TABMASK (TAB - 1)
#define ATAB 1024
#define ATABMASK (ATAB - 1)
#define GRID 64
#define BLK 256
#define GSZ (GRID * BLK)

__device__ unsigned int       g_Abits[MM / 32];
__device__ unsigned long long g_rowsig[NN];
__device__ unsigned long long g_colsig[NN];
__device__ unsigned long long g_tab[TAB];
__device__ unsigned int       g_minpos[TAB];
__device__ int                g_count[TAB];
__device__ int                g_slotrank[TAB];
__device__ int                g_slotid[MM];
__device__ unsigned int       g_aminpos[ATAB];
__device__ int                g_acount[ATAB];
__device__ int                g_arank[ATAB];
__device__ int4               g_mark4[MM / 4];
__device__ int4               g_rank4[MM / 4];
__device__ int                g_bsum[GRID];
__device__ unsigned int       g_barcnt;
__device__ unsigned int       g_bargen;

#define g_mark ((int*)g_mark4)
#define g_rank ((int*)g_rank4)

__device__ __forceinline__ void gsync() {
    __syncthreads();
    if (threadIdx.x == 0) {
        volatile unsigned int* vgen = &g_bargen;
        __threadfence();
        unsigned int gen = *vgen;
        if (atomicAdd(&g_barcnt, 1u) == GRID - 1) {
            g_barcnt = 0u;
            __threadfence();
            *vgen = gen + 1u;
        } else {
            while (*vgen == gen) { }
        }
        __threadfence();
    }
    __syncthreads();
}

__device__ __forceinline__ unsigned long long sm64(unsigned long long z) {
    z += 0x9E3779B97F4A7C15ULL;
    z = (z ^ (z >> 30)) * 0xBF58476D1CE4E5B9ULL;
    z = (z ^ (z >> 27)) * 0x94D049BB133111EBULL;
    return z ^ (z >> 31);
}

__device__ __forceinline__ unsigned int hash32(unsigned int x) {
    x ^= x >> 16; x *= 0x7feb352du;
    x ^= x >> 15; x *= 0x846ca68bu;
    x ^= x >> 16;
    return x;
}

__device__ __forceinline__ unsigned int abit(int idx) {
    return (g_Abits[idx >> 5] >> (idx & 31)) & 1u;
}

__device__ __forceinline__ unsigned int atomic_key(const int* __restrict__ x, int idx) {
    int i = idx >> 8;
    int j = idx & 255;
    unsigned int key = ((unsigned int)x[i] << 5) | ((unsigned int)x[j] << 1) | abit(idx);
    return key & ATABMASK;
}

// label of pair idx at the current layer
__device__ __forceinline__ int cur_label(int layer, const int* __restrict__ x, int idx) {
    if (layer == 0) return g_arank[atomic_key(x, idx)];
    return g_slotrank[(unsigned int)g_slotid[idx] & TABMASK];
}

__global__ void __launch_bounds__(BLK, 1)
k_all(const int* __restrict__ x, const int* __restrict__ ei, int E,
      float* __restrict__ out, int out_size) {
    int b = blockIdx.x, t = threadIdx.x;
    int gid = b * BLK + t;
    int lane = t & 31, w = t >> 5;

    __shared__ unsigned int sh_u32[ATAB];
    __shared__ int sh_boff[GRID];
    __shared__ int warp_sums[8];
    __shared__ int warp_excl[8];

    // ---------------- init ----------------
    for (int i = gid; i < out_size; i += GSZ) out[i] = 0.0f;
    for (int i = gid; i < MM / 32; i += GSZ) g_Abits[i] = 0u;
    for (int i = gid; i < TAB; i += GSZ) {
        g_tab[i] = 0ULL;
        g_minpos[i] = 0xFFFFFFFFu;
        g_count[i] = 0;
    }
    for (int i = gid; i < MM; i += GSZ) g_mark[i] = 0;
    if (gid < ATAB) { g_aminpos[gid] = 0xFFFFFFFFu; g_acount[gid] = 0; }
    gsync();

    // ---------------- edges ----------------
    for (int e = gid; e < E; e += GSZ) {
        unsigned int s = (unsigned int)ei[e] & 255u;
        unsigned int d = (unsigned int)ei[E + e] & 255u;
        unsigned int idx = s * NN + d;
        atomicOr(&g_Abits[idx >> 5], 1u << (idx & 31));
    }
    gsync();

    // ---------------- atomic insert ----------------
    for (int idx = gid; idx < MM; idx += GSZ) {
        int i = idx >> 8;
        int j = idx & 255;
        unsigned int pos = (i == j) ? (unsigned int)(NN * (NN - 1) + i)
                                    : (unsigned int)(i * (NN - 1) + (j < i ? j : j - 1));
        unsigned int key = atomic_key(x, idx);
        atomicMin(&g_aminpos[key], pos);
        atomicAdd(&g_acount[key], 1);
    }
    gsync();

    // ---------------- atomic rank + hist0 ----------------
    {
        #pragma unroll
        for (int u = 0; u < ATAB / BLK; u++) sh_u32[t + BLK * u] = g_aminpos[t + BLK * u];
        __syncthreads();
        int slot = b * 16 + (t >> 4);
        int lane16 = t & 15;
        unsigned int v = sh_u32[slot];
        int partial = 0;
        #pragma unroll 4
        for (int u = lane16; u < ATAB; u += 16) partial += (sh_u32[u] < v);
        #pragma unroll
        for (int off = 8; off > 0; off >>= 1)
            partial += __shfl_down_sync(0xFFFFFFFFu, partial, off, 16);
        if (lane16 == 0 && v != 0xFFFFFFFFu) {
            g_arank[slot] = partial;
            if (partial < out_size) out[partial] = (float)g_acount[slot];
        }
    }
    gsync();

    // ---------------- 2 refinement layers ----------------
    for (int layer = 0; layer < 2; layer++) {
        // ---- signatures: one warp per row/col task (8 tasks per block) ----
        {
            int task = b * 8 + w;              // 0..511
            bool isRow = task < NN;
            int rc = isRow ? task : task - NN;
            unsigned long long h = 0ULL;
            #pragma unroll
            for (int k = 0; k < 8; k++) {
                int e = lane * 8 + k;
                int idx = isRow ? ((rc << 8) + e) : ((e << 8) + rc);
                h += sm64((unsigned long long)(unsigned int)cur_label(layer, x, idx));
            }
            #pragma unroll
            for (int off = 16; off > 0; off >>= 1)
                h += __shfl_down_sync(0xFFFFFFFFu, h, off);
            if (lane == 0) {
                if (isRow) g_rowsig[rc] = h;
                else       g_colsig[rc] = h;
            }
        }
        gsync();

        // ---- insert into hash table ----
        for (int idx = gid; idx < MM; idx += GSZ) {
            int i = idx >> 8;
            int j = idx & 255;
            int lab = cur_label(layer, x, idx);
            unsigned long long key =
                sm64(g_rowsig[i] * 0xC2B2AE3D27D4EB4FULL
                   ^ g_colsig[j] * 0x165667B19E3779F9ULL
                   ^ ((unsigned long long)(unsigned int)lab + 1ULL)
                       * 0x9E3779B97F4A7C15ULL);
            unsigned long long stored = key | 1ULL;
            unsigned int h = hash32((unsigned int)key ^ (unsigned int)(key >> 32)) & TABMASK;
            for (;;) {
                unsigned long long old = atomicCAS(&g_tab[h], 0ULL, stored);
                if (old == 0ULL || old == stored) break;
                h = (h + 1) & TABMASK;
            }
            atomicMin(&g_minpos[h], (unsigned int)idx);
            atomicAdd(&g_count[h], 1);
            g_slotid[idx] = (int)h;
        }
        gsync();

        // ---- mark first-occurrence positions ----
        for (int s = gid; s < TAB; s += GSZ) {
            if (g_tab[s] != 0ULL) {
                unsigned int p = g_minpos[s];
                if (p < (unsigned int)MM) g_mark[p] = 1;
            }
        }
        gsync();

        // ---- per-block scan of chunk b (1024 ints as 256 int4), clear marks ----
        {
            int4 v = g_mark4[b * 256 + t];
            g_mark4[b * 256 + t] = make_int4(0, 0, 0, 0);
            int s01 = v.x + v.y;
            int s012 = s01 + v.z;
            int tot = s012 + v.w;
            int inc = tot;
            #pragma unroll
            for (int off = 1; off < 32; off <<= 1) {
                int n = __shfl_up_sync(0xFFFFFFFFu, inc, off);
                if (lane >= off) inc += n;
            }
            if (lane == 31) warp_sums[w] = inc;
            __syncthreads();
            if (t < 8) {
                int ws = warp_sums[t];
                int inc2 = ws;
                #pragma unroll
                for (int off = 1; off < 8; off <<= 1) {
                    int n = __shfl_up_sync(0xFFu, inc2, off);
                    if (t >= off) inc2 += n;
                }
                warp_excl[t] = inc2 - ws;
            }
            __syncthreads();
            int base = warp_excl[w] + inc - tot;
            int4 e;
            e.x = base;
            e.y = base + v.x;
            e.z = base + s01;
            e.w = base + s012;
            g_rank4[b * 256 + t] = e;
            if (t == 255) g_bsum[b] = warp_excl[7] + inc;
        }
        gsync();

        // ---- every block: warp-scan the 64 block sums into shared boff ----
        if (t < 32) {
            int v0 = g_bsum[2 * t];
            int v1 = g_bsum[2 * t + 1];
            int p = v0 + v1;
            int inc3 = p;
            #pragma unroll
            for (int off = 1; off < 32; off <<= 1) {
                int n = __shfl_up_sync(0xFFFFFFFFu, inc3, off);
                if (t >= off) inc3 += n;
            }
            int excl = inc3 - p;
            sh_boff[2 * t] = excl;
            sh_boff[2 * t + 1] = excl + v0;
        }
        __syncthreads();

        // ---- finish: histogram + slot ranks; clean table for next layer ----
        {
            int off0 = (layer + 1) * MM;
            int avail = out_size - off0;
            if (avail > MM) avail = MM;
            float* dst = out + off0;
            for (int s = gid; s < TAB; s += GSZ) {
                if (g_tab[s] != 0ULL) {
                    unsigned int p = g_minpos[s] & (MM - 1);
                    int r = (g_rank[p] + sh_boff[p >> 10]) & (MM - 1);
                    g_slotrank[s] = r;
                    if (r < avail) dst[r] = (float)g_count[s];
                    if (layer == 0) {
                        g_tab[s] = 0ULL;
                        g_minpos[s] = 0xFFFFFFFFu;
                        g_count[s] = 0;
                    }
                }
            }
        }
        if (layer == 0) gsync();
    }
}

// ---------------------------------------------------------------------------
extern "C" void kernel_launch(void* const* d_in, const int* in_sizes, int n_in,
                              void* d_out, int out_size) {
    int xi = 0, ei_i = 1;
    if (n_in >= 2 && in_sizes[0] > in_sizes[1]) { xi = 1; ei_i = 0; }
    const int* x  = (const int*)d_in[xi];
    const int* ei = (const int*)d_in[ei_i];
    int E = in_sizes[ei_i] / 2;
    if (E == 4 * 8192) E = 8192;
    float* out = (float*)d_out;

    k_all<<<GRID, BLK>>>(x, ei, E, out, out_size);
}

// round 10
// speedup vs baseline: 1.9163x; 1.9163x over previous
#include <cuda_runtime.h>
#include <stdint.h>

// ---------------------------------------------------------------------------
// TwoWL: 2-layer 2-WL coloring, N=256, M=65536. Output: 3 float32 histograms.
// 9-launch pipeline; labels are first-occurrence positions (minpos), so rank
// computation is off the critical path. Two hash tables (ping-pong) let layer
// 1 insertion overlap layer 0 histogram finalization.
// ---------------------------------------------------------------------------

#define NN 256
#define MM 65536
#define TAB 131072
#define TABMASK (TAB - 1)
#define ATAB 1024
#define ATABMASK (ATAB - 1)

__device__ unsigned int       g_Abits[MM / 32];
__device__ unsigned long long g_rowsig[NN];
__device__ unsigned long long g_colsig[NN];
__device__ unsigned long long g_tabA[TAB];
__device__ unsigned int       g_minposA[TAB];
__device__ int                g_countA[TAB];
__device__ unsigned long long g_tabB[TAB];
__device__ unsigned int       g_minposB[TAB];
__device__ int                g_countB[TAB];
__device__ int                g_slotid[MM];
__device__ unsigned int       g_aminpos[ATAB];
__device__ int                g_acount[ATAB];
__device__ int4               g_mark4[MM / 4];
__device__ int4               g_rank4[MM / 4];
__device__ int                g_bsum[64];

#define g_mark ((int*)g_mark4)
#define g_rank ((int*)g_rank4)

__device__ __forceinline__ unsigned long long sm64(unsigned long long z) {
    z += 0x9E3779B97F4A7C15ULL;
    z = (z ^ (z >> 30)) * 0xBF58476D1CE4E5B9ULL;
    z = (z ^ (z >> 27)) * 0x94D049BB133111EBULL;
    return z ^ (z >> 31);
}

__device__ __forceinline__ unsigned int hash32(unsigned int x) {
    x ^= x >> 16; x *= 0x7feb352du;
    x ^= x >> 15; x *= 0x846ca68bu;
    x ^= x >> 16;
    return x;
}

__device__ __forceinline__ unsigned int abit(int idx) {
    return (g_Abits[idx >> 5] >> (idx & 31)) & 1u;
}

__device__ __forceinline__ unsigned int atomic_key(const int* __restrict__ x, int idx) {
    int i = idx >> 8;
    int j = idx & 255;
    unsigned int key = ((unsigned int)x[i] << 5) | ((unsigned int)x[j] << 1) | abit(idx);
    return key & ATABMASK;
}

// ---------------------------------------------------------------------------
// L1: block 0 builds adjacency bitset (clear + edges, __syncthreads between);
//     blocks 1..255 clear everything else.
// ---------------------------------------------------------------------------
__global__ void k_init_edges(float* out, int out_size,
                             const int* __restrict__ ei, int E) {
    int b = blockIdx.x, t = threadIdx.x;
    if (b == 0) {
        for (int i = t; i < MM / 32; i += 256) g_Abits[i] = 0u;
        __syncthreads();
        for (int e = t; e < E; e += 256) {
            unsigned int s = (unsigned int)ei[e] & 255u;
            unsigned int d = (unsigned int)ei[E + e] & 255u;
            unsigned int idx = s * NN + d;
            atomicOr(&g_Abits[idx >> 5], 1u << (idx & 31));
        }
    } else {
        int gid = (b - 1) * 256 + t;
        int stride = 255 * 256;
        for (int i = gid; i < out_size; i += stride) out[i] = 0.0f;
        for (int i = gid; i < TAB; i += stride) {
            g_tabA[i] = 0ULL; g_minposA[i] = 0xFFFFFFFFu; g_countA[i] = 0;
            g_tabB[i] = 0ULL; g_minposB[i] = 0xFFFFFFFFu; g_countB[i] = 0;
        }
        for (int i = gid; i < MM; i += stride) g_mark[i] = 0;
        if (gid < ATAB) { g_aminpos[gid] = 0xFFFFFFFFu; g_acount[gid] = 0; }
    }
}

// ---------------------------------------------------------------------------
// L2: atomic-layer insert (direct 1024-entry table)
// ---------------------------------------------------------------------------
__global__ void k_insA(const int* __restrict__ x) {
    int idx = blockIdx.x * blockDim.x + threadIdx.x;
    if (idx >= MM) return;
    int i = idx >> 8;
    int j = idx & 255;
    unsigned int pos = (i == j) ? (unsigned int)(NN * (NN - 1) + i)
                                : (unsigned int)(i * (NN - 1) + (j < i ? j : j - 1));
    unsigned int key = atomic_key(x, idx);
    atomicMin(&g_aminpos[key], pos);
    atomicAdd(&g_acount[key], 1);
}

// ---------------------------------------------------------------------------
// Shared: block-per-task signature (task < 256: row, else col).
// Label source: mode 0 -> aminpos[atomic_key]; mode 1 -> minposA[slotid].
// ---------------------------------------------------------------------------
__device__ __forceinline__ void sig_block(int task, int t, int mode,
                                          const int* __restrict__ x) {
    __shared__ unsigned long long ws[8];
    int lane = t & 31, w = t >> 5;
    bool isRow = (task < NN);
    int rc = isRow ? task : task - NN;
    int idx = isRow ? ((rc << 8) + t) : ((t << 8) + rc);
    unsigned int lab;
    if (mode == 0) lab = g_aminpos[atomic_key(x, idx)];
    else           lab = g_minposA[(unsigned int)g_slotid[idx] & TABMASK];
    unsigned long long h = sm64((unsigned long long)lab);
    #pragma unroll
    for (int off = 16; off > 0; off >>= 1)
        h += __shfl_down_sync(0xFFFFFFFFu, h, off);
    if (lane == 0) ws[w] = h;
    __syncthreads();
    if (t < 8) {
        unsigned long long hh = ws[t];
        #pragma unroll
        for (int off = 4; off > 0; off >>= 1)
            hh += __shfl_down_sync(0xFFu, hh, off);
        if (t == 0) {
            if (isRow) g_rowsig[rc] = hh;
            else       g_colsig[rc] = hh;
        }
    }
}

// ---------------------------------------------------------------------------
// L3: blocks 0-511 sig0; blocks 512-575 rank atomic table -> hist0
// ---------------------------------------------------------------------------
__global__ void k_sig0_rankA(const int* __restrict__ x,
                             float* __restrict__ out0, int avail) {
    int b = blockIdx.x, t = threadIdx.x;
    if (b < 512) { sig_block(b, t, 0, x); return; }
    __shared__ unsigned int s[ATAB];
    #pragma unroll
    for (int u = 0; u < 4; u++) s[t + 256 * u] = g_aminpos[t + 256 * u];
    __syncthreads();
    int slot = (b - 512) * 16 + (t >> 4);
    int lane16 = t & 15;
    unsigned int v = s[slot];
    int partial = 0;
    #pragma unroll 4
    for (int u = lane16; u < ATAB; u += 16) partial += (s[u] < v);
    #pragma unroll
    for (int off = 8; off > 0; off >>= 1)
        partial += __shfl_down_sync(0xFFFFFFFFu, partial, off, 16);
    if (lane16 == 0 && v != 0xFFFFFFFFu && partial < avail)
        out0[partial] = (float)g_acount[slot];
}

// ---------------------------------------------------------------------------
// Hash insert (templated over table by pointer args)
// ---------------------------------------------------------------------------
__device__ __forceinline__ void ins_pair(int idx, unsigned int lab,
                                         unsigned long long* tab,
                                         unsigned int* minpos, int* count) {
    int i = idx >> 8;
    int j = idx & 255;
    unsigned long long key =
        sm64(g_rowsig[i] * 0xC2B2AE3D27D4EB4FULL
           ^ g_colsig[j] * 0x165667B19E3779F9ULL
           ^ ((unsigned long long)lab + 1ULL) * 0x9E3779B97F4A7C15ULL);
    unsigned long long stored = key | 1ULL;
    unsigned int h = hash32((unsigned int)key ^ (unsigned int)(key >> 32)) & TABMASK;
    for (;;) {
        unsigned long long old = atomicCAS(&tab[h], 0ULL, stored);
        if (old == 0ULL || old == stored) break;
        h = (h + 1) & TABMASK;
    }
    atomicMin(&minpos[h], (unsigned int)idx);
    atomicAdd(&count[h], 1);
    g_slotid[idx] = (int)h;
}

// L4: layer-0 insert into table A (labels from aminpos)
__global__ void k_ins0(const int* __restrict__ x) {
    int idx = blockIdx.x * blockDim.x + threadIdx.x;
    if (idx >= MM) return;
    ins_pair(idx, g_aminpos[atomic_key(x, idx)], g_tabA, g_minposA, g_countA);
}

// ---------------------------------------------------------------------------
// L5: blocks 0-511 sig1 (labels = minposA[slotid]); blocks 512-1023 mark0
// ---------------------------------------------------------------------------
__global__ void k_sig1_mark0(const int* __restrict__ x) {
    int b = blockIdx.x, t = threadIdx.x;
    if (b < 512) { sig_block(b, t, 1, x); return; }
    int s = (b - 512) * 256 + t;
    if (g_tabA[s] != 0ULL) g_mark[g_minposA[s] & (MM - 1)] = 1;
}

// ---------------------------------------------------------------------------
// Scan one 1024-int chunk (int4 x 256 threads); clears marks.
// ---------------------------------------------------------------------------
__device__ __forceinline__ void scan_block(int chunk, int t) {
    __shared__ int warp_sums[8];
    __shared__ int warp_excl[8];
    int lane = t & 31, w = t >> 5;
    int4 v = g_mark4[chunk * 256 + t];
    g_mark4[chunk * 256 + t] = make_int4(0, 0, 0, 0);
    int s01 = v.x + v.y;
    int s012 = s01 + v.z;
    int tot = s012 + v.w;
    int inc = tot;
    #pragma unroll
    for (int off = 1; off < 32; off <<= 1) {
        int n = __shfl_up_sync(0xFFFFFFFFu, inc, off);
        if (lane >= off) inc += n;
    }
    if (lane == 31) warp_sums[w] = inc;
    __syncthreads();
    if (t < 8) {
        int ws = warp_sums[t];
        int inc2 = ws;
        #pragma unroll
        for (int off = 1; off < 8; off <<= 1) {
            int n = __shfl_up_sync(0xFFu, inc2, off);
            if (t >= off) inc2 += n;
        }
        warp_excl[t] = inc2 - ws;
    }
    __syncthreads();
    int base = warp_excl[w] + inc - tot;
    int4 e;
    e.x = base;
    e.y = base + v.x;
    e.z = base + s01;
    e.w = base + s012;
    g_rank4[chunk * 256 + t] = e;
    if (t == 255) g_bsum[chunk] = warp_excl[7] + inc;
}

// L6: blocks 0-255 layer-1 insert into table B (labels = minposA[slotid]);
//     blocks 256-319 scan0.
__global__ void k_ins1_scan0() {
    int b = blockIdx.x, t = threadIdx.x;
    if (b < 256) {
        int idx = b * 256 + t;
        unsigned int lab = g_minposA[(unsigned int)g_slotid[idx] & TABMASK];
        ins_pair(idx, lab, g_tabB, g_minposB, g_countB);
        return;
    }
    scan_block(b - 256, t);
}

// ---------------------------------------------------------------------------
// finish: hist for one table using g_rank + per-block redundant boff scan.
// ---------------------------------------------------------------------------
__device__ __forceinline__ void finish_block(int sb, int t,
                                             const unsigned long long* tab,
                                             const unsigned int* minpos,
                                             const int* count,
                                             float* dst, int avail) {
    __shared__ int sh_boff[64];
    if (t < 32) {
        int v0 = g_bsum[2 * t];
        int v1 = g_bsum[2 * t + 1];
        int p = v0 + v1;
        int inc3 = p;
        #pragma unroll
        for (int off = 1; off < 32; off <<= 1) {
            int n = __shfl_up_sync(0xFFFFFFFFu, inc3, off);
            if (t >= off) inc3 += n;
        }
        int excl = inc3 - p;
        sh_boff[2 * t] = excl;
        sh_boff[2 * t + 1] = excl + v0;
    }
    __syncthreads();
    int s = sb * 256 + t;
    if (tab[s] != 0ULL) {
        unsigned int p = minpos[s] & (MM - 1);
        int r = (g_rank[p] + sh_boff[p >> 10]) & (MM - 1);
        if (r < avail) dst[r] = (float)count[s];
    }
}

// L7: blocks 0-511 mark1 (table B); blocks 512-1023 finish0 (table A -> hist1)
__global__ void k_mark1_finish0(float* __restrict__ out1, int avail) {
    int b = blockIdx.x, t = threadIdx.x;
    if (b < 512) {
        int s = b * 256 + t;
        if (g_tabB[s] != 0ULL) g_mark[g_minposB[s] & (MM - 1)] = 1;
        return;
    }
    finish_block(b - 512, t, g_tabA, g_minposA, g_countA, out1, avail);
}

// L8: scan1
__global__ void k_scan1() {
    scan_block(blockIdx.x, threadIdx.x);
}

// L9: finish1 (table B -> hist2)
__global__ void k_finish1(float* __restrict__ out2, int avail) {
    finish_block(blockIdx.x, threadIdx.x, g_tabB, g_minposB, g_countB, out2, avail);
}

// ---------------------------------------------------------------------------
extern "C" void kernel_launch(void* const* d_in, const int* in_sizes, int n_in,
                              void* d_out, int out_size) {
    int xi = 0, ei_i = 1;
    if (n_in >= 2 && in_sizes[0] > in_sizes[1]) { xi = 1; ei_i = 0; }
    const int* x  = (const int*)d_in[xi];
    const int* ei = (const int*)d_in[ei_i];
    int E = in_sizes[ei_i] / 2;
    if (E == 4 * 8192) E = 8192;
    float* out = (float*)d_out;

    int a0 = out_size < MM ? out_size : MM;
    int a1 = out_size - MM;     if (a1 > MM) a1 = MM; if (a1 < 0) a1 = 0;
    int a2 = out_size - 2 * MM; if (a2 > MM) a2 = MM; if (a2 < 0) a2 = 0;

    k_init_edges<<<256, 256>>>(out, out_size, ei, E);          // L1
    k_insA<<<256, 256>>>(x);                                   // L2
    k_sig0_rankA<<<576, 256>>>(x, out, a0);                    // L3
    k_ins0<<<256, 256>>>(x);                                   // L4
    k_sig1_mark0<<<1024, 256>>>(x);                            // L5
    k_ins1_scan0<<<320, 256>>>();                              // L6
    k_mark1_finish0<<<1024, 256>>>(out + MM, a1);              // L7
    k_scan1<<<64, 256>>>();                                    // L8
    k_finish1<<<512, 256>>>(out + 2 * MM, a2);                 // L9
}

// round 11
// speedup vs baseline: 2.1535x; 1.1238x over previous
#include <cuda_runtime.h>
#include <stdint.h>

// ---------------------------------------------------------------------------
// TwoWL: 2-layer 2-WL coloring, N=256, M=65536. Output: 3 float32 histograms.
//
// Key identity: the layer-(l+1) group of pair (i,j) is exactly
//     (rowclass_l(i), colclass_l(j), A[i,j])
// because the row/col multiset classes determine the per-node components of
// the label. So group keys live in 256*256*2 = 131072 values -> direct table
// (atomicMin of first-occurrence pos + atomicAdd count), no hashing.
// Classes are recomputed redundantly per consumer block from the multiset
// hash signatures (commutative 64-bit sum).
// ---------------------------------------------------------------------------

#define NN 256
#define MM 65536
#define TAB 131072                 // rc*512 + cc*2 + A
#define ATAB 1024
#define ATABMASK (ATAB - 1)

__device__ unsigned int       g_Abits[MM / 32];
__device__ unsigned long long g_rowsig0[NN];
__device__ unsigned long long g_colsig0[NN];
__device__ unsigned long long g_rowsig1[NN];
__device__ unsigned long long g_colsig1[NN];
__device__ unsigned int       g_minposA[TAB];
__device__ int                g_countA[TAB];
__device__ unsigned int       g_minposB[TAB];
__device__ int                g_countB[TAB];
__device__ unsigned int       g_aminpos[ATAB];
__device__ int                g_acount[ATAB];
__device__ int4               g_mark4[MM / 4];
__device__ int4               g_rank4[MM / 4];
__device__ int                g_bsum[64];

#define g_mark ((int*)g_mark4)
#define g_rank ((int*)g_rank4)

__device__ __forceinline__ unsigned long long sm64(unsigned long long z) {
    z += 0x9E3779B97F4A7C15ULL;
    z = (z ^ (z >> 30)) * 0xBF58476D1CE4E5B9ULL;
    z = (z ^ (z >> 27)) * 0x94D049BB133111EBULL;
    return z ^ (z >> 31);
}

__device__ __forceinline__ unsigned int abit(int idx) {
    return (g_Abits[idx >> 5] >> (idx & 31)) & 1u;
}

__device__ __forceinline__ unsigned int atomic_key(const int* __restrict__ x, int idx) {
    int i = idx >> 8;
    int j = idx & 255;
    unsigned int key = ((unsigned int)x[i] << 5) | ((unsigned int)x[j] << 1) | abit(idx);
    return key & ATABMASK;
}

// first index u in [0,256) with s[u] == v (class id)
__device__ __forceinline__ int min_eq_idx(const unsigned long long* s,
                                          unsigned long long v) {
    int best = 256;
    #pragma unroll 8
    for (int u = 0; u < NN; u++) {
        if (s[u] == v && u < best) best = u;
    }
    return best;
}

// ---------------------------------------------------------------------------
// L1: block 0 builds adjacency bitset; blocks 1..255 clear everything else.
// ---------------------------------------------------------------------------
__global__ void k_init_edges(float* out, int out_size,
                             const int* __restrict__ ei, int E) {
    int b = blockIdx.x, t = threadIdx.x;
    if (b == 0) {
        for (int i = t; i < MM / 32; i += 256) g_Abits[i] = 0u;
        __syncthreads();
        for (int e = t; e < E; e += 256) {
            unsigned int s = (unsigned int)ei[e] & 255u;
            unsigned int d = (unsigned int)ei[E + e] & 255u;
            unsigned int idx = s * NN + d;
            atomicOr(&g_Abits[idx >> 5], 1u << (idx & 31));
        }
    } else {
        int gid = (b - 1) * 256 + t;
        int stride = 255 * 256;
        for (int i = gid; i < out_size; i += stride) out[i] = 0.0f;
        for (int i = gid; i < TAB; i += stride) {
            g_minposA[i] = 0xFFFFFFFFu; g_countA[i] = 0;
            g_minposB[i] = 0xFFFFFFFFu; g_countB[i] = 0;
        }
        for (int i = gid; i < MM; i += stride) g_mark[i] = 0;
        if (gid < ATAB) { g_aminpos[gid] = 0xFFFFFFFFu; g_acount[gid] = 0; }
    }
}

// ---------------------------------------------------------------------------
// L2: atomic-layer insert (direct 1024-entry table, special pos ordering)
// ---------------------------------------------------------------------------
__global__ void k_insA(const int* __restrict__ x) {
    int idx = blockIdx.x * blockDim.x + threadIdx.x;
    if (idx >= MM) return;
    int i = idx >> 8;
    int j = idx & 255;
    unsigned int pos = (i == j) ? (unsigned int)(NN * (NN - 1) + i)
                                : (unsigned int)(i * (NN - 1) + (j < i ? j : j - 1));
    unsigned int key = atomic_key(x, idx);
    atomicMin(&g_aminpos[key], pos);
    atomicAdd(&g_acount[key], 1);
}

// ---------------------------------------------------------------------------
// L3: blocks 0-511 sig0 (labels = aminpos[key0]); blocks 512-575 rankA->hist0
// ---------------------------------------------------------------------------
__global__ void k_sig0_rankA(const int* __restrict__ x,
                             float* __restrict__ out0, int avail) {
    int b = blockIdx.x, t = threadIdx.x;
    if (b < 512) {
        __shared__ unsigned long long ws[8];
        int lane = t & 31, w = t >> 5;
        bool isRow = (b < NN);
        int rc = isRow ? b : b - NN;
        int idx = isRow ? ((rc << 8) + t) : ((t << 8) + rc);
        unsigned long long h =
            sm64((unsigned long long)g_aminpos[atomic_key(x, idx)]);
        #pragma unroll
        for (int off = 16; off > 0; off >>= 1)
            h += __shfl_down_sync(0xFFFFFFFFu, h, off);
        if (lane == 0) ws[w] = h;
        __syncthreads();
        if (t < 8) {
            unsigned long long hh = ws[t];
            #pragma unroll
            for (int off = 4; off > 0; off >>= 1)
                hh += __shfl_down_sync(0xFFu, hh, off);
            if (t == 0) {
                if (isRow) g_rowsig0[rc] = hh;
                else       g_colsig0[rc] = hh;
            }
        }
        return;
    }
    __shared__ unsigned int s[ATAB];
    #pragma unroll
    for (int u = 0; u < 4; u++) s[t + 256 * u] = g_aminpos[t + 256 * u];
    __syncthreads();
    int slot = (b - 512) * 16 + (t >> 4);
    int lane16 = t & 15;
    unsigned int v = s[slot];
    int partial = 0;
    #pragma unroll 4
    for (int u = lane16; u < ATAB; u += 16) partial += (s[u] < v);
    #pragma unroll
    for (int off = 8; off > 0; off >>= 1)
        partial += __shfl_down_sync(0xFFFFFFFFu, partial, off, 16);
    if (lane16 == 0 && v != 0xFFFFFFFFu && partial < avail)
        out0[partial] = (float)g_acount[slot];
}

// ---------------------------------------------------------------------------
// L4: layer-0 -> layer-1 insert into direct table A.
// Block b handles row i=b. key = rc0(b)*512 + cc0(j)*2 + A.
// ---------------------------------------------------------------------------
__global__ void k_ins0() {
    __shared__ unsigned long long srow[NN];
    __shared__ unsigned long long scol[NN];
    __shared__ int rc_sh;
    int b = blockIdx.x, t = threadIdx.x;
    srow[t] = g_rowsig0[t];
    scol[t] = g_colsig0[t];
    if (t == 0) rc_sh = 256;
    __syncthreads();
    if (srow[t] == srow[b]) atomicMin(&rc_sh, t);
    int cc = min_eq_idx(scol, scol[t]);
    __syncthreads();
    int idx = (b << 8) + t;
    unsigned int key = (unsigned int)rc_sh * 512u + (unsigned int)cc * 2u + abit(idx);
    atomicMin(&g_minposA[key], (unsigned int)idx);
    atomicAdd(&g_countA[key], 1);
}

// ---------------------------------------------------------------------------
// L5: blocks 0-511 sig1 (labels = minposA[key1], classes recomputed from
//     sig0 arrays); blocks 512-1023 mark0.
// ---------------------------------------------------------------------------
__global__ void k_sig1_mark0() {
    int b = blockIdx.x, t = threadIdx.x;
    if (b < 512) {
        __shared__ unsigned long long srow[NN];
        __shared__ unsigned long long scol[NN];
        __shared__ unsigned long long ws[8];
        __shared__ int own_sh;
        int lane = t & 31, w = t >> 5;
        srow[t] = g_rowsig0[t];
        scol[t] = g_colsig0[t];
        if (t == 0) own_sh = 256;
        __syncthreads();
        bool isRow = (b < NN);
        int rcix = isRow ? b : b - NN;
        unsigned int lab;
        if (isRow) {
            if (srow[t] == srow[rcix]) atomicMin(&own_sh, t);   // rc0(i)
            int cc = min_eq_idx(scol, scol[t]);                 // cc0(t)
            __syncthreads();
            int idx = (rcix << 8) + t;
            unsigned int key = (unsigned int)own_sh * 512u
                             + (unsigned int)cc * 2u + abit(idx);
            lab = g_minposA[key];
        } else {
            if (scol[t] == scol[rcix]) atomicMin(&own_sh, t);   // cc0(j)
            int rc = min_eq_idx(srow, srow[t]);                 // rc0(t)
            __syncthreads();
            int idx = (t << 8) + rcix;
            unsigned int key = (unsigned int)rc * 512u
                             + (unsigned int)own_sh * 2u + abit(idx);
            lab = g_minposA[key];
        }
        unsigned long long h = sm64((unsigned long long)lab);
        #pragma unroll
        for (int off = 16; off > 0; off >>= 1)
            h += __shfl_down_sync(0xFFFFFFFFu, h, off);
        if (lane == 0) ws[w] = h;
        __syncthreads();
        if (t < 8) {
            unsigned long long hh = ws[t];
            #pragma unroll
            for (int off = 4; off > 0; off >>= 1)
                hh += __shfl_down_sync(0xFFu, hh, off);
            if (t == 0) {
                if (isRow) g_rowsig1[rcix] = hh;
                else       g_colsig1[rcix] = hh;
            }
        }
        return;
    }
    int s = (b - 512) * 256 + t;
    if (g_countA[s] > 0) g_mark[g_minposA[s] & (MM - 1)] = 1;
}

// ---------------------------------------------------------------------------
// Scan one 1024-int chunk (int4 x 256 threads); clears marks.
// ---------------------------------------------------------------------------
__device__ __forceinline__ void scan_block(int chunk, int t) {
    __shared__ int warp_sums[8];
    __shared__ int warp_excl[8];
    int lane = t & 31, w = t >> 5;
    int4 v = g_mark4[chunk * 256 + t];
    g_mark4[chunk * 256 + t] = make_int4(0, 0, 0, 0);
    int s01 = v.x + v.y;
    int s012 = s01 + v.z;
    int tot = s012 + v.w;
    int inc = tot;
    #pragma unroll
    for (int off = 1; off < 32; off <<= 1) {
        int n = __shfl_up_sync(0xFFFFFFFFu, inc, off);
        if (lane >= off) inc += n;
    }
    if (lane == 31) warp_sums[w] = inc;
    __syncthreads();
    if (t < 8) {
        int ws = warp_sums[t];
        int inc2 = ws;
        #pragma unroll
        for (int off = 1; off < 8; off <<= 1) {
            int n = __shfl_up_sync(0xFFu, inc2, off);
            if (t >= off) inc2 += n;
        }
        warp_excl[t] = inc2 - ws;
    }
    __syncthreads();
    int base = warp_excl[w] + inc - tot;
    int4 e;
    e.x = base;
    e.y = base + v.x;
    e.z = base + s01;
    e.w = base + s012;
    g_rank4[chunk * 256 + t] = e;
    if (t == 255) g_bsum[chunk] = warp_excl[7] + inc;
}

// ---------------------------------------------------------------------------
// L6: blocks 0-255 layer-1 -> layer-2 insert into direct table B
//     (classes recomputed from sig1 arrays); blocks 256-319 scan0.
// ---------------------------------------------------------------------------
__global__ void k_ins1_scan0() {
    int b = blockIdx.x, t = threadIdx.x;
    if (b < 256) {
        __shared__ unsigned long long srow[NN];
        __shared__ unsigned long long scol[NN];
        __shared__ int rc_sh;
        srow[t] = g_rowsig1[t];
        scol[t] = g_colsig1[t];
        if (t == 0) rc_sh = 256;
        __syncthreads();
        if (srow[t] == srow[b]) atomicMin(&rc_sh, t);
        int cc = min_eq_idx(scol, scol[t]);
        __syncthreads();
        int idx = (b << 8) + t;
        unsigned int key = (unsigned int)rc_sh * 512u
                         + (unsigned int)cc * 2u + abit(idx);
        atomicMin(&g_minposB[key], (unsigned int)idx);
        atomicAdd(&g_countB[key], 1);
        return;
    }
    scan_block(b - 256, t);
}

// ---------------------------------------------------------------------------
// finish: histogram for one direct table via g_rank + redundant boff scan.
// ---------------------------------------------------------------------------
__device__ __forceinline__ void finish_block(int sb, int t,
                                             const unsigned int* minpos,
                                             const int* count,
                                             float* dst, int avail) {
    __shared__ int sh_boff[64];
    if (t < 32) {
        int v0 = g_bsum[2 * t];
        int v1 = g_bsum[2 * t + 1];
        int p = v0 + v1;
        int inc3 = p;
        #pragma unroll
        for (int off = 1; off < 32; off <<= 1) {
            int n = __shfl_up_sync(0xFFFFFFFFu, inc3, off);
            if (t >= off) inc3 += n;
        }
        int excl = inc3 - p;
        sh_boff[2 * t] = excl;
        sh_boff[2 * t + 1] = excl + v0;
    }
    __syncthreads();
    int s = sb * 256 + t;
    int c = count[s];
    if (c > 0) {
        unsigned int p = minpos[s] & (MM - 1);
        int r = (g_rank[p] + sh_boff[p >> 10]) & (MM - 1);
        if (r < avail) dst[r] = (float)c;
    }
}

// L7: blocks 0-511 mark1 (table B); blocks 512-1023 finish0 (A -> hist1)
__global__ void k_mark1_finish0(float* __restrict__ out1, int avail) {
    int b = blockIdx.x, t = threadIdx.x;
    if (b < 512) {
        int s = b * 256 + t;
        if (g_countB[s] > 0) g_mark[g_minposB[s] & (MM - 1)] = 1;
        return;
    }
    finish_block(b - 512, t, g_minposA, g_countA, out1, avail);
}

// L8: scan1
__global__ void k_scan1() {
    scan_block(blockIdx.x, threadIdx.x);
}

// L9: finish1 (table B -> hist2)
__global__ void k_finish1(float* __restrict__ out2, int avail) {
    finish_block(blockIdx.x, threadIdx.x, g_minposB, g_countB, out2, avail);
}

// ---------------------------------------------------------------------------
extern "C" void kernel_launch(void* const* d_in, const int* in_sizes, int n_in,
                              void* d_out, int out_size) {
    int xi = 0, ei_i = 1;
    if (n_in >= 2 && in_sizes[0] > in_sizes[1]) { xi = 1; ei_i = 0; }
    const int* x  = (const int*)d_in[xi];
    const int* ei = (const int*)d_in[ei_i];
    int E = in_sizes[ei_i] / 2;
    if (E == 4 * 8192) E = 8192;
    float* out = (float*)d_out;

    int a0 = out_size < MM ? out_size : MM;
    int a1 = out_size - MM;     if (a1 > MM) a1 = MM; if (a1 < 0) a1 = 0;
    int a2 = out_size - 2 * MM; if (a2 > MM) a2 = MM; if (a2 < 0) a2 = 0;

    k_init_edges<<<256, 256>>>(out, out_size, ei, E);   // L1
    k_insA<<<256, 256>>>(x);                            // L2
    k_sig0_rankA<<<576, 256>>>(x, out, a0);             // L3
    k_ins0<<<256, 256>>>();                             // L4
    k_sig1_mark0<<<1024, 256>>>();                      // L5
    k_ins1_scan0<<<320, 256>>>();                       // L6
    k_mark1_finish0<<<1024, 256>>>(out + MM, a1);       // L7
    k_scan1<<<64, 256>>>();                             // L8
    k_finish1<<<512, 256>>>(out + 2 * MM, a2);          // L9
}

// round 12
// speedup vs baseline: 2.8247x; 1.3117x over previous
#include <cuda_runtime.h>
#include <stdint.h>

// ---------------------------------------------------------------------------
// TwoWL: 2-layer 2-WL coloring, N=256, M=65536. Output: 3 float32 histograms.
//
// Group key of pair (i,j) at layer l+1 is (rowclass_l(i), colclass_l(j), A),
// living in 256*256*2 = 131072 values -> direct table (atomicMin pos +
// atomicAdd count). Classes come from commutative 64-bit multiset-hash
// signatures; per-block class lookup uses a 512-slot shared hash table.
// ---------------------------------------------------------------------------

#define NN 256
#define MM 65536
#define TAB 131072                 // rc*512 + cc*2 + A
#define ATAB 1024
#define ATABMASK (ATAB - 1)

__device__ unsigned int       g_Abits[MM / 32];
__device__ unsigned long long g_rowsig0[NN];
__device__ unsigned long long g_colsig0[NN];
__device__ unsigned long long g_rowsig1[NN];
__device__ unsigned long long g_colsig1[NN];
__device__ unsigned int       g_minposA[TAB];
__device__ int                g_countA[TAB];
__device__ unsigned int       g_minposB[TAB];
__device__ int                g_countB[TAB];
__device__ unsigned int       g_aminpos[ATAB];
__device__ int                g_acount[ATAB];
__device__ int4               g_mark4[MM / 4];
__device__ int4               g_rank4[MM / 4];
__device__ int                g_bsum[64];

#define g_mark ((int*)g_mark4)
#define g_rank ((int*)g_rank4)

__device__ __forceinline__ unsigned long long sm64(unsigned long long z) {
    z += 0x9E3779B97F4A7C15ULL;
    z = (z ^ (z >> 30)) * 0xBF58476D1CE4E5B9ULL;
    z = (z ^ (z >> 27)) * 0x94D049BB133111EBULL;
    return z ^ (z >> 31);
}

__device__ __forceinline__ unsigned int abit(int idx) {
    return (g_Abits[idx >> 5] >> (idx & 31)) & 1u;
}

__device__ __forceinline__ unsigned int atomic_key(const int* __restrict__ x, int idx) {
    int i = idx >> 8;
    int j = idx & 255;
    unsigned int key = ((unsigned int)x[i] << 5) | ((unsigned int)x[j] << 1) | abit(idx);
    return key & ATABMASK;
}

// ---------------------------------------------------------------------------
// Per-block class lookup: class(t) = min u with s[u]==s[t], via shared hash.
// hk: 512 x u64 keys, hm: 512 x int min-index. Caller provides smem.
// ---------------------------------------------------------------------------
__device__ __forceinline__ int classify256(const unsigned long long* s, int t,
                                           unsigned long long* hk, int* hm) {
    hk[t] = 0ULL; hk[t + 256] = 0ULL;
    hm[t] = 256;  hm[t + 256] = 256;
    __syncthreads();
    unsigned long long v = s[t] | 0x8000000000000000ULL;   // nonzero key
    unsigned int h0 = (unsigned int)((v * 0xFF51AFD7ED558CCDULL) >> 55) & 511u;
    // phase 1: insert (duplicates across slots possible; harmless)
    unsigned int h = h0;
    for (;;) {
        unsigned long long old = atomicCAS(&hk[h], 0ULL, v);
        if (old == 0ULL || old == v) break;
        h = (h + 1) & 511u;
    }
    __syncthreads();
    // phase 2: first matching slot along the frozen probe path (deterministic)
    h = h0;
    while (hk[h] != v) h = (h + 1) & 511u;
    atomicMin(&hm[h], t);
    __syncthreads();
    return hm[h];
}

// ---------------------------------------------------------------------------
// L1: block 0 builds adjacency bitset; blocks 1..255 clear everything else.
// ---------------------------------------------------------------------------
__global__ void k_init_edges(float* out, int out_size,
                             const int* __restrict__ ei, int E) {
    int b = blockIdx.x, t = threadIdx.x;
    if (b == 0) {
        for (int i = t; i < MM / 32; i += 256) g_Abits[i] = 0u;
        __syncthreads();
        for (int e = t; e < E; e += 256) {
            unsigned int s = (unsigned int)ei[e] & 255u;
            unsigned int d = (unsigned int)ei[E + e] & 255u;
            unsigned int idx = s * NN + d;
            atomicOr(&g_Abits[idx >> 5], 1u << (idx & 31));
        }
    } else {
        int gid = (b - 1) * 256 + t;
        int stride = 255 * 256;
        for (int i = gid; i < out_size; i += stride) out[i] = 0.0f;
        for (int i = gid; i < TAB; i += stride) {
            g_minposA[i] = 0xFFFFFFFFu; g_countA[i] = 0;
            g_minposB[i] = 0xFFFFFFFFu; g_countB[i] = 0;
        }
        for (int i = gid; i < MM; i += stride) g_mark[i] = 0;
        if (gid < ATAB) { g_aminpos[gid] = 0xFFFFFFFFu; g_acount[gid] = 0; }
    }
}

// ---------------------------------------------------------------------------
// L2: atomic-layer insert (direct 1024-entry table, special pos ordering)
// ---------------------------------------------------------------------------
__global__ void k_insA(const int* __restrict__ x) {
    int idx = blockIdx.x * blockDim.x + threadIdx.x;
    if (idx >= MM) return;
    int i = idx >> 8;
    int j = idx & 255;
    unsigned int pos = (i == j) ? (unsigned int)(NN * (NN - 1) + i)
                                : (unsigned int)(i * (NN - 1) + (j < i ? j : j - 1));
    unsigned int key = atomic_key(x, idx);
    atomicMin(&g_aminpos[key], pos);
    atomicAdd(&g_acount[key], 1);
}

// ---------------------------------------------------------------------------
// L3: blocks 0-511 sig0 (labels = aminpos[key0]); blocks 512-575 rankA->hist0
// ---------------------------------------------------------------------------
__global__ void k_sig0_rankA(const int* __restrict__ x,
                             float* __restrict__ out0, int avail) {
    int b = blockIdx.x, t = threadIdx.x;
    if (b < 512) {
        __shared__ unsigned long long ws[8];
        int lane = t & 31, w = t >> 5;
        bool isRow = (b < NN);
        int rc = isRow ? b : b - NN;
        int idx = isRow ? ((rc << 8) + t) : ((t << 8) + rc);
        unsigned long long h =
            sm64((unsigned long long)g_aminpos[atomic_key(x, idx)]);
        #pragma unroll
        for (int off = 16; off > 0; off >>= 1)
            h += __shfl_down_sync(0xFFFFFFFFu, h, off);
        if (lane == 0) ws[w] = h;
        __syncthreads();
        if (t < 8) {
            unsigned long long hh = ws[t];
            #pragma unroll
            for (int off = 4; off > 0; off >>= 1)
                hh += __shfl_down_sync(0xFFu, hh, off);
            if (t == 0) {
                if (isRow) g_rowsig0[rc] = hh;
                else       g_colsig0[rc] = hh;
            }
        }
        return;
    }
    __shared__ unsigned int s[ATAB];
    #pragma unroll
    for (int u = 0; u < 4; u++) s[t + 256 * u] = g_aminpos[t + 256 * u];
    __syncthreads();
    int slot = (b - 512) * 16 + (t >> 4);
    int lane16 = t & 15;
    unsigned int v = s[slot];
    int partial = 0;
    #pragma unroll 4
    for (int u = lane16; u < ATAB; u += 16) partial += (s[u] < v);
    #pragma unroll
    for (int off = 8; off > 0; off >>= 1)
        partial += __shfl_down_sync(0xFFFFFFFFu, partial, off, 16);
    if (lane16 == 0 && v != 0xFFFFFFFFu && partial < avail)
        out0[partial] = (float)g_acount[slot];
}

// ---------------------------------------------------------------------------
// L4: layer-0 -> layer-1 insert into direct table A.
// Block b = row i. key = rc0(b)*512 + cc0(j)*2 + A.
// ---------------------------------------------------------------------------
__global__ void k_ins0() {
    __shared__ unsigned long long srow[NN];
    __shared__ unsigned long long scol[NN];
    __shared__ unsigned long long hk[512];
    __shared__ int hm[512];
    __shared__ int rc_sh;
    int b = blockIdx.x, t = threadIdx.x;
    srow[t] = g_rowsig0[t];
    scol[t] = g_colsig0[t];
    if (t == 0) rc_sh = 256;
    __syncthreads();
    if (srow[t] == srow[b]) atomicMin(&rc_sh, t);
    int cc = classify256(scol, t, hk, hm);
    __syncthreads();
    int idx = (b << 8) + t;
    unsigned int key = (unsigned int)rc_sh * 512u + (unsigned int)cc * 2u + abit(idx);
    atomicMin(&g_minposA[key], (unsigned int)idx);
    atomicAdd(&g_countA[key], 1);
}

// ---------------------------------------------------------------------------
// L5: blocks 0-511 sig1 (labels = minposA[key1]); blocks 512-1023 mark0.
// ---------------------------------------------------------------------------
__global__ void k_sig1_mark0() {
    int b = blockIdx.x, t = threadIdx.x;
    if (b < 512) {
        __shared__ unsigned long long srow[NN];
        __shared__ unsigned long long scol[NN];
        __shared__ unsigned long long hk[512];
        __shared__ int hm[512];
        __shared__ unsigned long long ws[8];
        __shared__ int own_sh;
        int lane = t & 31, w = t >> 5;
        srow[t] = g_rowsig0[t];
        scol[t] = g_colsig0[t];
        if (t == 0) own_sh = 256;
        __syncthreads();
        bool isRow = (b < NN);
        int rcix = isRow ? b : b - NN;
        unsigned int lab;
        if (isRow) {
            if (srow[t] == srow[rcix]) atomicMin(&own_sh, t);   // rc0(i)
            int cc = classify256(scol, t, hk, hm);              // cc0(t)
            __syncthreads();
            int idx = (rcix << 8) + t;
            unsigned int key = (unsigned int)own_sh * 512u
                             + (unsigned int)cc * 2u + abit(idx);
            lab = g_minposA[key];
        } else {
            if (scol[t] == scol[rcix]) atomicMin(&own_sh, t);   // cc0(j)
            int rc = classify256(srow, t, hk, hm);              // rc0(t)
            __syncthreads();
            int idx = (t << 8) + rcix;
            unsigned int key = (unsigned int)rc * 512u
                             + (unsigned int)own_sh * 2u + abit(idx);
            lab = g_minposA[key];
        }
        unsigned long long h = sm64((unsigned long long)lab);
        #pragma unroll
        for (int off = 16; off > 0; off >>= 1)
            h += __shfl_down_sync(0xFFFFFFFFu, h, off);
        if (lane == 0) ws[w] = h;
        __syncthreads();
        if (t < 8) {
            unsigned long long hh = ws[t];
            #pragma unroll
            for (int off = 4; off > 0; off >>= 1)
                hh += __shfl_down_sync(0xFFu, hh, off);
            if (t == 0) {
                if (isRow) g_rowsig1[rcix] = hh;
                else       g_colsig1[rcix] = hh;
            }
        }
        return;
    }
    int s = (b - 512) * 256 + t;
    if (g_countA[s] > 0) g_mark[g_minposA[s] & (MM - 1)] = 1;
}

// ---------------------------------------------------------------------------
// Scan one 1024-int chunk (int4 x 256 threads); clears marks.
// ---------------------------------------------------------------------------
__device__ __forceinline__ void scan_block(int chunk, int t) {
    __shared__ int warp_sums[8];
    __shared__ int warp_excl[8];
    int lane = t & 31, w = t >> 5;
    int4 v = g_mark4[chunk * 256 + t];
    g_mark4[chunk * 256 + t] = make_int4(0, 0, 0, 0);
    int s01 = v.x + v.y;
    int s012 = s01 + v.z;
    int tot = s012 + v.w;
    int inc = tot;
    #pragma unroll
    for (int off = 1; off < 32; off <<= 1) {
        int n = __shfl_up_sync(0xFFFFFFFFu, inc, off);
        if (lane >= off) inc += n;
    }
    if (lane == 31) warp_sums[w] = inc;
    __syncthreads();
    if (t < 8) {
        int ws = warp_sums[t];
        int inc2 = ws;
        #pragma unroll
        for (int off = 1; off < 8; off <<= 1) {
            int n = __shfl_up_sync(0xFFu, inc2, off);
            if (t >= off) inc2 += n;
        }
        warp_excl[t] = inc2 - ws;
    }
    __syncthreads();
    int base = warp_excl[w] + inc - tot;
    int4 e;
    e.x = base;
    e.y = base + v.x;
    e.z = base + s01;
    e.w = base + s012;
    g_rank4[chunk * 256 + t] = e;
    if (t == 255) g_bsum[chunk] = warp_excl[7] + inc;
}

// ---------------------------------------------------------------------------
// L6: blocks 0-255 layer-1 -> layer-2 insert into direct table B;
//     blocks 256-319 scan0.
// ---------------------------------------------------------------------------
__global__ void k_ins1_scan0() {
    int b = blockIdx.x, t = threadIdx.x;
    if (b < 256) {
        __shared__ unsigned long long srow[NN];
        __shared__ unsigned long long scol[NN];
        __shared__ unsigned long long hk[512];
        __shared__ int hm[512];
        __shared__ int rc_sh;
        srow[t] = g_rowsig1[t];
        scol[t] = g_colsig1[t];
        if (t == 0) rc_sh = 256;
        __syncthreads();
        if (srow[t] == srow[b]) atomicMin(&rc_sh, t);
        int cc = classify256(scol, t, hk, hm);
        __syncthreads();
        int idx = (b << 8) + t;
        unsigned int key = (unsigned int)rc_sh * 512u
                         + (unsigned int)cc * 2u + abit(idx);
        atomicMin(&g_minposB[key], (unsigned int)idx);
        atomicAdd(&g_countB[key], 1);
        return;
    }
    scan_block(b - 256, t);
}

// ---------------------------------------------------------------------------
// finish: histogram for one direct table via g_rank + redundant boff scan.
// ---------------------------------------------------------------------------
__device__ __forceinline__ void finish_block(int sb, int t,
                                             const unsigned int* minpos,
                                             const int* count,
                                             float* dst, int avail) {
    __shared__ int sh_boff[64];
    if (t < 32) {
        int v0 = g_bsum[2 * t];
        int v1 = g_bsum[2 * t + 1];
        int p = v0 + v1;
        int inc3 = p;
        #pragma unroll
        for (int off = 1; off < 32; off <<= 1) {
            int n = __shfl_up_sync(0xFFFFFFFFu, inc3, off);
            if (t >= off) inc3 += n;
        }
        int excl = inc3 - p;
        sh_boff[2 * t] = excl;
        sh_boff[2 * t + 1] = excl + v0;
    }
    __syncthreads();
    int s = sb * 256 + t;
    int c = count[s];
    if (c > 0) {
        unsigned int p = minpos[s] & (MM - 1);
        int r = (g_rank[p] + sh_boff[p >> 10]) & (MM - 1);
        if (r < avail) dst[r] = (float)c;
    }
}

// L7: blocks 0-511 mark1 (table B); blocks 512-1023 finish0 (A -> hist1)
__global__ void k_mark1_finish0(float* __restrict__ out1, int avail) {
    int b = blockIdx.x, t = threadIdx.x;
    if (b < 512) {
        int s = b * 256 + t;
        if (g_countB[s] > 0) g_mark[g_minposB[s] & (MM - 1)] = 1;
        return;
    }
    finish_block(b - 512, t, g_minposA, g_countA, out1, avail);
}

// L8: scan1
__global__ void k_scan1() {
    scan_block(blockIdx.x, threadIdx.x);
}

// L9: finish1 (table B -> hist2)
__global__ void k_finish1(float* __restrict__ out2, int avail) {
    finish_block(blockIdx.x, threadIdx.x, g_minposB, g_countB, out2, avail);
}

// ---------------------------------------------------------------------------
extern "C" void kernel_launch(void* const* d_in, const int* in_sizes, int n_in,
                              void* d_out, int out_size) {
    int xi = 0, ei_i = 1;
    if (n_in >= 2 && in_sizes[0] > in_sizes[1]) { xi = 1; ei_i = 0; }
    const int* x  = (const int*)d_in[xi];
    const int* ei = (const int*)d_in[ei_i];
    int E = in_sizes[ei_i] / 2;
    if (E == 4 * 8192) E = 8192;
    float* out = (float*)d_out;

    int a0 = out_size < MM ? out_size : MM;
    int a1 = out_size - MM;     if (a1 > MM) a1 = MM; if (a1 < 0) a1 = 0;
    int a2 = out_size - 2 * MM; if (a2 > MM) a2 = MM; if (a2 < 0) a2 = 0;

    k_init_edges<<<256, 256>>>(out, out_size, ei, E);   // L1
    k_insA<<<256, 256>>>(x);                            // L2
    k_sig0_rankA<<<576, 256>>>(x, out, a0);             // L3
    k_ins0<<<256, 256>>>();                             // L4
    k_sig1_mark0<<<1024, 256>>>();                      // L5
    k_ins1_scan0<<<320, 256>>>();                       // L6
    k_mark1_finish0<<<1024, 256>>>(out + MM, a1);       // L7
    k_scan1<<<64, 256>>>();                             // L8
    k_finish1<<<512, 256>>>(out + 2 * MM, a2);          // L9
}